// round 5
// baseline (speedup 1.0000x reference)
#include <cuda_runtime.h>

#define BB 128   // batch
#define TT 128   // timesteps
#define NN 100   // subactors
#define HH 16    // hidden
#define SS 6     // state
#define GG 48    // 3*H gates

typedef unsigned long long ull;

// ---- packed f32x2 helpers ----
__device__ __forceinline__ ull ffma2(ull a, ull b, ull c) {
    ull d; asm("fma.rn.f32x2 %0, %1, %2, %3;" : "=l"(d) : "l"(a), "l"(b), "l"(c)); return d;
}
__device__ __forceinline__ ull pack2(float lo, float hi) {
    ull r; asm("mov.b64 %0, {%1, %2};" : "=l"(r) : "f"(lo), "f"(hi)); return r;
}
__device__ __forceinline__ float2 unpack2(ull v) {
    float2 f; asm("mov.b64 {%0, %1}, %2;" : "=f"(f.x), "=f"(f.y) : "l"(v)); return f;
}
__device__ __forceinline__ float hadd2(ull v) { float2 f = unpack2(v); return f.x + f.y; }
// ---- fast activations (MUFU-based, ~1e-6 rel err) ----
__device__ __forceinline__ float fex2(float x) { float y; asm("ex2.approx.f32 %0, %1;" : "=f"(y) : "f"(x)); return y; }
__device__ __forceinline__ float frcp(float x) { float y; asm("rcp.approx.f32 %0, %1;" : "=f"(y) : "f"(x)); return y; }
__device__ __forceinline__ float fsigmoid(float x) {
    return frcp(1.0f + fex2(-1.4426950408889634f * x));
}
__device__ __forceinline__ float ftanh_(float x) {
    return fmaf(-2.0f, frcp(1.0f + fex2(2.8853900817779268f * x)), 1.0f);
}

// K-pair smem layout, lane-major (16B stride -> conflict-free, broadcast across groups).
// Lane l (0..7) owns: r gates {2l,2l+1}, z {16+2l,16+2l+1}, n {32+2l,32+2l+1},
// MLP outputs {2l,2l+1}. ulonglong2 = (gate 2l K-pair, gate 2l+1 K-pair).
struct __align__(16) SmemW {
    ulonglong2 whr[8][8];   // [kk][lane]
    ulonglong2 whz[8][8];
    ulonglong2 whn[8][8];
    ulonglong2 wir[3][8];
    ulonglong2 wiz[3][8];
    ulonglong2 win[3][8];
    ulonglong2 w1k[8][8];
    ulonglong2 w2k[8][8];
    ulonglong2 br[8], bz[8], bxn[8], bhn[8], b1v[8], b2v[8];  // (bias,0) pairs
    ull w3v[8];
    float b3v;
};

__global__ void __launch_bounds__(64)
actor_fused_kernel(const float* __restrict__ x,
                   const float* __restrict__ Wih, const float* __restrict__ Whh,
                   const float* __restrict__ bih, const float* __restrict__ bhh,
                   const float* __restrict__ W1,  const float* __restrict__ b1,
                   const float* __restrict__ W2,  const float* __restrict__ b2,
                   const float* __restrict__ W3,  const float* __restrict__ b3,
                   float* __restrict__ out)
{
    __shared__ SmemW sw;
    const int n   = blockIdx.x >> 3;      // subactor
    const int qb  = blockIdx.x & 7;       // batch eighth
    const int tid = threadIdx.x;
    const int l   = tid & 7;              // lane within 8-lane group
    const int g   = tid >> 3;             // group (0..7)

    // ---------------- one-time weight staging ----------------
    {
        const float* Wh  = Whh + n * GG * HH;
        const float* Wi  = Wih + n * GG * SS;
        const float* W1N = W1 + n * HH * HH;
        const float* W2N = W2 + n * HH * HH;
        const int kk = tid >> 3, ll = tid & 7;      // one (kk,ll) per thread
        const int gr = 2 * ll, gz = 16 + 2 * ll, gn = 32 + 2 * ll;
        sw.whr[kk][ll] = make_ulonglong2(
            pack2(Wh[gr * HH + 2 * kk],       Wh[gr * HH + 2 * kk + 1]),
            pack2(Wh[(gr + 1) * HH + 2 * kk], Wh[(gr + 1) * HH + 2 * kk + 1]));
        sw.whz[kk][ll] = make_ulonglong2(
            pack2(Wh[gz * HH + 2 * kk],       Wh[gz * HH + 2 * kk + 1]),
            pack2(Wh[(gz + 1) * HH + 2 * kk], Wh[(gz + 1) * HH + 2 * kk + 1]));
        sw.whn[kk][ll] = make_ulonglong2(
            pack2(Wh[gn * HH + 2 * kk],       Wh[gn * HH + 2 * kk + 1]),
            pack2(Wh[(gn + 1) * HH + 2 * kk], Wh[(gn + 1) * HH + 2 * kk + 1]));
        sw.w1k[kk][ll] = make_ulonglong2(
            pack2(W1N[(2 * ll) * HH + 2 * kk],     W1N[(2 * ll) * HH + 2 * kk + 1]),
            pack2(W1N[(2 * ll + 1) * HH + 2 * kk], W1N[(2 * ll + 1) * HH + 2 * kk + 1]));
        sw.w2k[kk][ll] = make_ulonglong2(
            pack2(W2N[(2 * ll) * HH + 2 * kk],     W2N[(2 * ll) * HH + 2 * kk + 1]),
            pack2(W2N[(2 * ll + 1) * HH + 2 * kk], W2N[(2 * ll + 1) * HH + 2 * kk + 1]));
        if (kk < 3) {
            sw.wir[kk][ll] = make_ulonglong2(
                pack2(Wi[gr * SS + 2 * kk],       Wi[gr * SS + 2 * kk + 1]),
                pack2(Wi[(gr + 1) * SS + 2 * kk], Wi[(gr + 1) * SS + 2 * kk + 1]));
            sw.wiz[kk][ll] = make_ulonglong2(
                pack2(Wi[gz * SS + 2 * kk],       Wi[gz * SS + 2 * kk + 1]),
                pack2(Wi[(gz + 1) * SS + 2 * kk], Wi[(gz + 1) * SS + 2 * kk + 1]));
            sw.win[kk][ll] = make_ulonglong2(
                pack2(Wi[gn * SS + 2 * kk],       Wi[gn * SS + 2 * kk + 1]),
                pack2(Wi[(gn + 1) * SS + 2 * kk], Wi[(gn + 1) * SS + 2 * kk + 1]));
        }
        if (tid < 8) {
            const float* bi = bih + n * GG;
            const float* bh = bhh + n * GG;
            sw.br[tid]  = make_ulonglong2(pack2(bi[2 * tid] + bh[2 * tid], 0.0f),
                                          pack2(bi[2 * tid + 1] + bh[2 * tid + 1], 0.0f));
            sw.bz[tid]  = make_ulonglong2(pack2(bi[16 + 2 * tid] + bh[16 + 2 * tid], 0.0f),
                                          pack2(bi[17 + 2 * tid] + bh[17 + 2 * tid], 0.0f));
            sw.bxn[tid] = make_ulonglong2(pack2(bi[32 + 2 * tid], 0.0f),
                                          pack2(bi[33 + 2 * tid], 0.0f));
            sw.bhn[tid] = make_ulonglong2(pack2(bh[32 + 2 * tid], 0.0f),
                                          pack2(bh[33 + 2 * tid], 0.0f));
            sw.b1v[tid] = make_ulonglong2(pack2(b1[n * HH + 2 * tid], 0.0f),
                                          pack2(b1[n * HH + 2 * tid + 1], 0.0f));
            sw.b2v[tid] = make_ulonglong2(pack2(b2[n * HH + 2 * tid], 0.0f),
                                          pack2(b2[n * HH + 2 * tid + 1], 0.0f));
            sw.w3v[tid] = pack2(W3[n * HH + 2 * tid], W3[n * HH + 2 * tid + 1]);
        }
        if (tid == 0) sw.b3v = b3[n];
    }
    __syncthreads();

    // ---------------- promote per-lane constants to registers ----------------
    const ulonglong2 Rbr = sw.br[l], Rbz = sw.bz[l], Rbx = sw.bxn[l], Rbh = sw.bhn[l];
    const ulonglong2 Rb1 = sw.b1v[l], Rb2 = sw.b2v[l];
    const ull Rw3 = sw.w3v[l];
    const float Rb3 = sw.b3v;
    ulonglong2 Rw2[8];
#pragma unroll
    for (int kk = 0; kk < 8; kk++) Rw2[kk] = sw.w2k[kk][l];

    // ---------------- per-group state: 2 sequences ----------------
    const int b0 = qb * 16 + g * 2;
    const int xstride = NN * SS;

    ull hd[2][8];
#pragma unroll
    for (int s = 0; s < 2; s++)
#pragma unroll
        for (int i = 0; i < 8; i++) hd[s][i] = 0ULL;

    const float* xps[2];
#pragma unroll
    for (int s = 0; s < 2; s++)
        xps[s] = x + (long long)(b0 + s) * TT * xstride + n * SS;

    float* op = out + n * (BB * TT) + (b0 + (l & 1)) * TT;
    float ybuf[4];

#pragma unroll 1
    for (int t = 0; t < TT; t++) {
        // --- x loads (issued early; consumed after h-loop) ---
        ull xv[2][3];
#pragma unroll
        for (int s = 0; s < 2; s++) {
            const float2* px = reinterpret_cast<const float2*>(xps[s]);
            float2 a = __ldg(px), bq = __ldg(px + 1), c = __ldg(px + 2);
            xv[s][0] = pack2(a.x, a.y);
            xv[s][1] = pack2(bq.x, bq.y);
            xv[s][2] = pack2(c.x, c.y);
            xps[s] += xstride;
        }

        // --- K-pair accumulators, bias-folded from registers ---
        ull ra[2][2], za[2][2], xa[2][2], ha[2][2];
#pragma unroll
        for (int s = 0; s < 2; s++) {
            ra[s][0] = Rbr.x; ra[s][1] = Rbr.y;
            za[s][0] = Rbz.x; za[s][1] = Rbz.y;
            xa[s][0] = Rbx.x; xa[s][1] = Rbx.y;
            ha[s][0] = Rbh.x; ha[s][1] = Rbh.y;
        }
        // --- h contribution ---
#pragma unroll
        for (int kk = 0; kk < 8; kk++) {
            ulonglong2 wr = sw.whr[kk][l], wz = sw.whz[kk][l], wn = sw.whn[kk][l];
#pragma unroll
            for (int s = 0; s < 2; s++) {
                ull hk = hd[s][kk];
                ra[s][0] = ffma2(hk, wr.x, ra[s][0]); ra[s][1] = ffma2(hk, wr.y, ra[s][1]);
                za[s][0] = ffma2(hk, wz.x, za[s][0]); za[s][1] = ffma2(hk, wz.y, za[s][1]);
                ha[s][0] = ffma2(hk, wn.x, ha[s][0]); ha[s][1] = ffma2(hk, wn.y, ha[s][1]);
            }
        }
        // --- x contribution ---
#pragma unroll
        for (int kk = 0; kk < 3; kk++) {
            ulonglong2 wr = sw.wir[kk][l], wz = sw.wiz[kk][l], wn = sw.win[kk][l];
#pragma unroll
            for (int s = 0; s < 2; s++) {
                ull xk = xv[s][kk];
                ra[s][0] = ffma2(xk, wr.x, ra[s][0]); ra[s][1] = ffma2(xk, wr.y, ra[s][1]);
                za[s][0] = ffma2(xk, wz.x, za[s][0]); za[s][1] = ffma2(xk, wz.y, za[s][1]);
                xa[s][0] = ffma2(xk, wn.x, xa[s][0]); xa[s][1] = ffma2(xk, wn.y, xa[s][1]);
            }
        }

        // --- gates + update of owned h pair ---
        ull own[2];
#pragma unroll
        for (int s = 0; s < 2; s++) {
            float r0 = fsigmoid(hadd2(ra[s][0]));
            float r1 = fsigmoid(hadd2(ra[s][1]));
            float z0 = fsigmoid(hadd2(za[s][0]));
            float z1 = fsigmoid(hadd2(za[s][1]));
            float n0 = ftanh_(fmaf(r0, hadd2(ha[s][0]), hadd2(xa[s][0])));
            float n1 = ftanh_(fmaf(r1, hadd2(ha[s][1]), hadd2(xa[s][1])));
            float2 hold = unpack2(hd[s][l]);
            float h0 = fmaf(z0, hold.x - n0, n0);
            float h1 = fmaf(z1, hold.y - n1, n1);
            own[s] = pack2(h0, h1);
        }
        // --- gather full h per seq ---
#pragma unroll
        for (int s = 0; s < 2; s++) {
#pragma unroll
            for (int i = 0; i < 8; i++)
                hd[s][i] = __shfl_sync(0xFFFFFFFFu, own[s], i, 8);
        }

        // --- MLP layer 1 ---
        ull a1[2][2];
#pragma unroll
        for (int s = 0; s < 2; s++) { a1[s][0] = Rb1.x; a1[s][1] = Rb1.y; }
#pragma unroll
        for (int kk = 0; kk < 8; kk++) {
            ulonglong2 w = sw.w1k[kk][l];
#pragma unroll
            for (int s = 0; s < 2; s++) {
                a1[s][0] = ffma2(hd[s][kk], w.x, a1[s][0]);
                a1[s][1] = ffma2(hd[s][kk], w.y, a1[s][1]);
            }
        }
        ull y1own[2];
#pragma unroll
        for (int s = 0; s < 2; s++)
            y1own[s] = pack2(fmaxf(hadd2(a1[s][0]), 0.0f), fmaxf(hadd2(a1[s][1]), 0.0f));

        // --- MLP layer 2: register weights, broadcast y1 on the fly ---
        ull a2[2][2];
#pragma unroll
        for (int s = 0; s < 2; s++) { a2[s][0] = Rb2.x; a2[s][1] = Rb2.y; }
#pragma unroll
        for (int src = 0; src < 8; src++) {
#pragma unroll
            for (int s = 0; s < 2; s++) {
                ull yp = __shfl_sync(0xFFFFFFFFu, y1own[s], src, 8);
                a2[s][0] = ffma2(yp, Rw2[src].x, a2[s][0]);
                a2[s][1] = ffma2(yp, Rw2[src].y, a2[s][1]);
            }
        }

        // --- layer 3 + cross-lane reduce ---
        float sums[2];
#pragma unroll
        for (int s = 0; s < 2; s++) {
            ull y2p = pack2(fmaxf(hadd2(a2[s][0]), 0.0f), fmaxf(hadd2(a2[s][1]), 0.0f));
            float ps = hadd2(ffma2(y2p, Rw3, 0ULL));
            ps += __shfl_xor_sync(0xFFFFFFFFu, ps, 1, 8);
            ps += __shfl_xor_sync(0xFFFFFFFFu, ps, 2, 8);
            ps += __shfl_xor_sync(0xFFFFFFFFu, ps, 4, 8);
            sums[s] = ps;
        }
        float mysum = ((l & 1) == 0) ? sums[0] : sums[1];
        ybuf[t & 3] = fmaxf(mysum + Rb3, 0.0f);
        if ((t & 3) == 3 && l < 2) {
            *reinterpret_cast<float4*>(op + t - 3) =
                make_float4(ybuf[0], ybuf[1], ybuf[2], ybuf[3]);
        }
    }
}

extern "C" void kernel_launch(void* const* d_in, const int* in_sizes, int n_in,
                              void* d_out, int out_size)
{
    (void)in_sizes; (void)n_in; (void)out_size;
    const float* x   = (const float*)d_in[0];
    const float* Wih = (const float*)d_in[1];
    const float* Whh = (const float*)d_in[2];
    const float* bih = (const float*)d_in[3];
    const float* bhh = (const float*)d_in[4];
    const float* W1  = (const float*)d_in[5];
    const float* b1  = (const float*)d_in[6];
    const float* W2  = (const float*)d_in[7];
    const float* b2  = (const float*)d_in[8];
    const float* W3  = (const float*)d_in[9];
    const float* b3  = (const float*)d_in[10];
    float* out = (float*)d_out;

    actor_fused_kernel<<<NN * 8, 64>>>(x, Wih, Whh, bih, bhh, W1, b1, W2, b2, W3, b3, out);
}

// round 6
// speedup vs baseline: 1.6738x; 1.6738x over previous
#include <cuda_runtime.h>

#define BB 128   // batch
#define TT 128   // timesteps
#define NN 100   // subactors
#define HH 16    // hidden
#define SS 6     // state
#define GG 48    // 3*H gates

typedef unsigned long long ull;

// ---- packed f32x2 helpers ----
__device__ __forceinline__ ull ffma2(ull a, ull b, ull c) {
    ull d; asm("fma.rn.f32x2 %0, %1, %2, %3;" : "=l"(d) : "l"(a), "l"(b), "l"(c)); return d;
}
__device__ __forceinline__ ull pack2(float lo, float hi) {
    ull r; asm("mov.b64 %0, {%1, %2};" : "=l"(r) : "f"(lo), "f"(hi)); return r;
}
__device__ __forceinline__ float2 unpack2(ull v) {
    float2 f; asm("mov.b64 {%0, %1}, %2;" : "=f"(f.x), "=f"(f.y) : "l"(v)); return f;
}
__device__ __forceinline__ ull fadd2(ull a, ull b) {
    ull d; asm("add.rn.f32x2 %0, %1, %2;" : "=l"(d) : "l"(a), "l"(b)); return d;
}
// ---- fast activations (MUFU-based, ~1e-6 rel err) ----
__device__ __forceinline__ float fex2(float x) { float y; asm("ex2.approx.f32 %0, %1;" : "=f"(y) : "f"(x)); return y; }
__device__ __forceinline__ float frcp(float x) { float y; asm("rcp.approx.f32 %0, %1;" : "=f"(y) : "f"(x)); return y; }
__device__ __forceinline__ float fsigmoid(float x) {
    return frcp(1.0f + fex2(-1.4426950408889634f * x));
}
__device__ __forceinline__ float ftanh_(float x) {
    return fmaf(-2.0f, frcp(1.0f + fex2(2.8853900817779268f * x)), 1.0f);
}

// Dup-packed weights: each ulonglong2 = ((w_k, w_k), (w_{k+1}, w_{k+1})) for gate/output
// owned by lane l. Lane l (0..15) owns r-gate l, z-gate l, n-gate l, MLP out l.
struct __align__(16) SmemW {
    ulonglong2 whr2[8][16];   // [k2][lane]  k = 2*k2, 2*k2+1 of Whh row (r)
    ulonglong2 whz2[8][16];
    ulonglong2 whn2[8][16];
    ulonglong2 wir2[3][16];   // x weights (k<6)
    ulonglong2 wiz2[3][16];
    ulonglong2 win2[3][16];
    ulonglong2 w1d [8][16];   // MLP1
};

__global__ void __launch_bounds__(64)
actor_fused_kernel(const float* __restrict__ x,
                   const float* __restrict__ Wih, const float* __restrict__ Whh,
                   const float* __restrict__ bih, const float* __restrict__ bhh,
                   const float* __restrict__ W1,  const float* __restrict__ b1,
                   const float* __restrict__ W2,  const float* __restrict__ b2,
                   const float* __restrict__ W3,  const float* __restrict__ b3,
                   float* __restrict__ out)
{
    __shared__ SmemW sw;
    // h / y1 broadcast buffers: [parity][group][pair][k(padded 20)]
    __shared__ __align__(16) ull hbuf[2][4][2][20];
    __shared__ __align__(16) ull ybuf1[2][4][2][20];

    const int n   = blockIdx.x >> 3;      // subactor
    const int qb  = blockIdx.x & 7;       // batch eighth (16 seqs)
    const int tid = threadIdx.x;
    const int l   = tid & 15;             // lane in 16-lane group
    const int g   = tid >> 4;             // group 0..3

    // ---------------- one-time weight staging (dup-packed) ----------------
    {
        const float* Wh  = Whh + n * GG * HH;
        const float* Wi  = Wih + n * GG * SS;
        const float* W1N = W1 + n * HH * HH;
        for (int i = tid; i < 8 * 16; i += 64) {
            int k2 = i >> 4, ll = i & 15;
            float a, b2_;
            a = Wh[ll * HH + 2 * k2];        b2_ = Wh[ll * HH + 2 * k2 + 1];
            sw.whr2[k2][ll] = make_ulonglong2(pack2(a, a), pack2(b2_, b2_));
            a = Wh[(16 + ll) * HH + 2 * k2]; b2_ = Wh[(16 + ll) * HH + 2 * k2 + 1];
            sw.whz2[k2][ll] = make_ulonglong2(pack2(a, a), pack2(b2_, b2_));
            a = Wh[(32 + ll) * HH + 2 * k2]; b2_ = Wh[(32 + ll) * HH + 2 * k2 + 1];
            sw.whn2[k2][ll] = make_ulonglong2(pack2(a, a), pack2(b2_, b2_));
            a = W1N[ll * HH + 2 * k2];       b2_ = W1N[ll * HH + 2 * k2 + 1];
            sw.w1d[k2][ll] = make_ulonglong2(pack2(a, a), pack2(b2_, b2_));
        }
        for (int i = tid; i < 3 * 16; i += 64) {
            int k2 = i >> 4, ll = i & 15;
            float a, b2_;
            a = Wi[ll * SS + 2 * k2];        b2_ = Wi[ll * SS + 2 * k2 + 1];
            sw.wir2[k2][ll] = make_ulonglong2(pack2(a, a), pack2(b2_, b2_));
            a = Wi[(16 + ll) * SS + 2 * k2]; b2_ = Wi[(16 + ll) * SS + 2 * k2 + 1];
            sw.wiz2[k2][ll] = make_ulonglong2(pack2(a, a), pack2(b2_, b2_));
            a = Wi[(32 + ll) * SS + 2 * k2]; b2_ = Wi[(32 + ll) * SS + 2 * k2 + 1];
            sw.win2[k2][ll] = make_ulonglong2(pack2(a, a), pack2(b2_, b2_));
        }
        // zero parity-0 h buffer (h starts at 0)
        for (int i = tid; i < 4 * 2 * 20; i += 64)
            hbuf[0][i / 40][(i / 20) & 1][i % 20] = 0ULL;
    }

    // per-lane register constants (direct gmem loads, one-time)
    const float bi_r = bih[n * GG + l]       + bhh[n * GG + l];
    const float bi_z = bih[n * GG + 16 + l]  + bhh[n * GG + 16 + l];
    const ull Rbr = pack2(bi_r, bi_r);
    const ull Rbz = pack2(bi_z, bi_z);
    const float bxn = bih[n * GG + 32 + l];
    const float bhn = bhh[n * GG + 32 + l];
    const ull Rbx = pack2(bxn, bxn);
    const ull Rbh = pack2(bhn, bhn);
    const float b1s = b1[n * HH + l], b2s = b2[n * HH + l];
    const ull Rb1 = pack2(b1s, b1s), Rb2 = pack2(b2s, b2s);
    const float w3s = W3[n * HH + l];
    const ull Rw3 = pack2(w3s, w3s);
    const float Rb3 = b3[n];
    ulonglong2 Rw2[8];
    {
        const float* W2N = W2 + n * HH * HH + l * HH;
#pragma unroll
        for (int k2 = 0; k2 < 8; k2++) {
            float a = W2N[2 * k2], bb = W2N[2 * k2 + 1];
            Rw2[k2] = make_ulonglong2(pack2(a, a), pack2(bb, bb));
        }
    }
    __syncthreads();

    // ---------------- per-group state: 4 sequences (2 packed pairs) ----------------
    const int b0 = qb * 16 + g * 4;
    const int xstride = NN * SS;
    const float* xps[4];
#pragma unroll
    for (int s = 0; s < 4; s++)
        xps[s] = x + (long long)(b0 + s) * TT * xstride + n * SS;

    ull own[2];                 // this lane's h value, packed (s0,s1)/(s2,s3)
    own[0] = 0ULL; own[1] = 0ULL;

    float* op = out + n * (BB * TT) + (b0 + l) * TT;   // valid for l<4
    float ybuf[4];

    // prefetch t=0 x (all lanes load same addresses -> L1 broadcast)
    float2 pn[4][3];
#pragma unroll
    for (int s = 0; s < 4; s++) {
        const float2* px = reinterpret_cast<const float2*>(xps[s]);
        pn[s][0] = __ldg(px); pn[s][1] = __ldg(px + 1); pn[s][2] = __ldg(px + 2);
    }

#pragma unroll 1
    for (int t = 0; t < TT; t++) {
        const int par = t & 1;

        // pack current x into seq-pairs, then issue prefetch for t+1
        ull xp[2][6];
#pragma unroll
        for (int p = 0; p < 2; p++) {
#pragma unroll
            for (int j = 0; j < 3; j++) {
                xp[p][2 * j]     = pack2(pn[2 * p][j].x, pn[2 * p + 1][j].x);
                xp[p][2 * j + 1] = pack2(pn[2 * p][j].y, pn[2 * p + 1][j].y);
            }
        }
        {
            const bool more = (t + 1 < TT);
#pragma unroll
            for (int s = 0; s < 4; s++) {
                xps[s] += more ? xstride : 0;
                const float2* px = reinterpret_cast<const float2*>(xps[s]);
                pn[s][0] = __ldg(px); pn[s][1] = __ldg(px + 1); pn[s][2] = __ldg(px + 2);
            }
        }

        __syncwarp();   // prev step's writes/reads ordered vs this step's hbuf reads

        // --- gate accumulators (seq-packed), biases folded ---
        ull ra[2] = { Rbr, Rbr }, za[2] = { Rbz, Rbz };
        ull xa[2] = { Rbx, Rbx }, ha[2] = { Rbh, Rbh };

        // h contribution: h_{t-1} from hbuf[par]
#pragma unroll
        for (int k2 = 0; k2 < 8; k2++) {
            ulonglong2 wr = sw.whr2[k2][l], wz = sw.whz2[k2][l], wn = sw.whn2[k2][l];
            ulonglong2 h0 = *reinterpret_cast<const ulonglong2*>(&hbuf[par][g][0][2 * k2]);
            ulonglong2 h1 = *reinterpret_cast<const ulonglong2*>(&hbuf[par][g][1][2 * k2]);
            ra[0] = ffma2(h0.x, wr.x, ra[0]); ra[0] = ffma2(h0.y, wr.y, ra[0]);
            ra[1] = ffma2(h1.x, wr.x, ra[1]); ra[1] = ffma2(h1.y, wr.y, ra[1]);
            za[0] = ffma2(h0.x, wz.x, za[0]); za[0] = ffma2(h0.y, wz.y, za[0]);
            za[1] = ffma2(h1.x, wz.x, za[1]); za[1] = ffma2(h1.y, wz.y, za[1]);
            ha[0] = ffma2(h0.x, wn.x, ha[0]); ha[0] = ffma2(h0.y, wn.y, ha[0]);
            ha[1] = ffma2(h1.x, wn.x, ha[1]); ha[1] = ffma2(h1.y, wn.y, ha[1]);
        }
        // x contribution
#pragma unroll
        for (int k2 = 0; k2 < 3; k2++) {
            ulonglong2 wr = sw.wir2[k2][l], wz = sw.wiz2[k2][l], wn = sw.win2[k2][l];
#pragma unroll
            for (int p = 0; p < 2; p++) {
                ull x0 = xp[p][2 * k2], x1 = xp[p][2 * k2 + 1];
                ra[p] = ffma2(x0, wr.x, ra[p]); ra[p] = ffma2(x1, wr.y, ra[p]);
                za[p] = ffma2(x0, wz.x, za[p]); za[p] = ffma2(x1, wz.y, za[p]);
                xa[p] = ffma2(x0, wn.x, xa[p]); xa[p] = ffma2(x1, wn.y, xa[p]);
            }
        }

        // --- gates + state update (scalar tail per packed pair) ---
#pragma unroll
        for (int p = 0; p < 2; p++) {
            float2 rv = unpack2(ra[p]);
            float r0 = fsigmoid(rv.x), r1 = fsigmoid(rv.y);
            float2 zv = unpack2(za[p]);
            float z0 = fsigmoid(zv.x), z1 = fsigmoid(zv.y);
            ull npre = ffma2(pack2(r0, r1), ha[p], xa[p]);
            float2 nv = unpack2(npre);
            float n0 = ftanh_(nv.x), n1 = ftanh_(nv.y);
            float2 hv = unpack2(own[p]);
            float h0 = fmaf(z0, hv.x - n0, n0);
            float h1 = fmaf(z1, hv.y - n1, n1);
            own[p] = pack2(h0, h1);
            hbuf[par ^ 1][g][p][l] = own[p];
        }
        __syncwarp();   // h_t visible to whole group

        // --- MLP layer 1 ---
        ull a1[2] = { Rb1, Rb1 };
#pragma unroll
        for (int k2 = 0; k2 < 8; k2++) {
            ulonglong2 w = sw.w1d[k2][l];
            ulonglong2 h0 = *reinterpret_cast<const ulonglong2*>(&hbuf[par ^ 1][g][0][2 * k2]);
            ulonglong2 h1 = *reinterpret_cast<const ulonglong2*>(&hbuf[par ^ 1][g][1][2 * k2]);
            a1[0] = ffma2(h0.x, w.x, a1[0]); a1[0] = ffma2(h0.y, w.y, a1[0]);
            a1[1] = ffma2(h1.x, w.x, a1[1]); a1[1] = ffma2(h1.y, w.y, a1[1]);
        }
#pragma unroll
        for (int p = 0; p < 2; p++) {
            float2 v = unpack2(a1[p]);
            ybuf1[par][g][p][l] = pack2(fmaxf(v.x, 0.0f), fmaxf(v.y, 0.0f));
        }
        __syncwarp();   // y1 visible

        // --- MLP layer 2 (weights in registers) ---
        ull a2[2] = { Rb2, Rb2 };
#pragma unroll
        for (int k2 = 0; k2 < 8; k2++) {
            ulonglong2 y0 = *reinterpret_cast<const ulonglong2*>(&ybuf1[par][g][0][2 * k2]);
            ulonglong2 y1 = *reinterpret_cast<const ulonglong2*>(&ybuf1[par][g][1][2 * k2]);
            a2[0] = ffma2(y0.x, Rw2[k2].x, a2[0]); a2[0] = ffma2(y0.y, Rw2[k2].y, a2[0]);
            a2[1] = ffma2(y1.x, Rw2[k2].x, a2[1]); a2[1] = ffma2(y1.y, Rw2[k2].y, a2[1]);
        }

        // --- layer 3 + cross-lane reduce (over 16 lanes) ---
        ull ps[2];
#pragma unroll
        for (int p = 0; p < 2; p++) {
            float2 v = unpack2(a2[p]);
            ull y2p = pack2(fmaxf(v.x, 0.0f), fmaxf(v.y, 0.0f));
            ps[p] = ffma2(y2p, Rw3, 0ULL);
        }
#pragma unroll
        for (int off = 1; off < 16; off <<= 1) {
            ps[0] = fadd2(ps[0], __shfl_xor_sync(0xFFFFFFFFu, ps[0], off, 16));
            ps[1] = fadd2(ps[1], __shfl_xor_sync(0xFFFFFFFFu, ps[1], off, 16));
        }
        // lane l<4 owns seq b0+l: (pair = l>>1, half = l&1)
        float2 p0 = unpack2(ps[0]), p1 = unpack2(ps[1]);
        float mysum = (l == 0) ? p0.x : (l == 1) ? p0.y : (l == 2) ? p1.x : p1.y;
        ybuf[t & 3] = fmaxf(mysum + Rb3, 0.0f);
        if ((t & 3) == 3 && l < 4) {
            *reinterpret_cast<float4*>(op + t - 3) =
                make_float4(ybuf[0], ybuf[1], ybuf[2], ybuf[3]);
        }
    }
}

extern "C" void kernel_launch(void* const* d_in, const int* in_sizes, int n_in,
                              void* d_out, int out_size)
{
    (void)in_sizes; (void)n_in; (void)out_size;
    const float* x   = (const float*)d_in[0];
    const float* Wih = (const float*)d_in[1];
    const float* Whh = (const float*)d_in[2];
    const float* bih = (const float*)d_in[3];
    const float* bhh = (const float*)d_in[4];
    const float* W1  = (const float*)d_in[5];
    const float* b1  = (const float*)d_in[6];
    const float* W2  = (const float*)d_in[7];
    const float* b2  = (const float*)d_in[8];
    const float* W3  = (const float*)d_in[9];
    const float* b3  = (const float*)d_in[10];
    float* out = (float*)d_out;

    actor_fused_kernel<<<NN * 8, 64>>>(x, Wih, Whh, bih, bhh, W1, b1, W2, b2, W3, b3, out);
}